// round 4
// baseline (speedup 1.0000x reference)
#include <cuda_runtime.h>
#include <cstdint>

#define DIM   192
#define HEADS 6
#define HDIM  32
#define NTOK  64
#define NWIN  4096

// ---------------------------------------------------------------------------
// Scratch (static device globals — no allocation in kernel_launch)
// ---------------------------------------------------------------------------
// qkv laid out as (b, s, h, n, d): each (b,s,h) tile is a contiguous 64x32 block
__device__ float g_qkv[(size_t)NWIN * 3 * HEADS * NTOK * HDIM];   // ~604 MB
__device__ float g_att[(size_t)NWIN * NTOK * DIM];                // ~201 MB
__device__ float g_bias[HEADS * NTOK * NTOK];                     // 96 KB

// ---------------------------------------------------------------------------
// Packed f32x2 helpers (Blackwell FFMA2 path — 2 FMAs per instruction)
// ---------------------------------------------------------------------------
__device__ __forceinline__ unsigned long long pk2(float x) {
    unsigned long long r;
    unsigned int b = __float_as_uint(x);
    asm("mov.b64 %0, {%1, %1};" : "=l"(r) : "r"(b));
    return r;
}
__device__ __forceinline__ unsigned long long pk2f(float lo, float hi) {
    unsigned long long r;
    asm("mov.b64 %0, {%1, %2};" : "=l"(r) : "r"(__float_as_uint(lo)), "r"(__float_as_uint(hi)));
    return r;
}
__device__ __forceinline__ float2 upk2(unsigned long long v) {
    unsigned int lo, hi;
    asm("mov.b64 {%0, %1}, %2;" : "=r"(lo), "=r"(hi) : "l"(v));
    return make_float2(__uint_as_float(lo), __uint_as_float(hi));
}
__device__ __forceinline__ void ffma2(unsigned long long& d,
                                      unsigned long long a,
                                      unsigned long long b) {
    asm("fma.rn.f32x2 %0, %1, %2, %0;" : "+l"(d) : "l"(a), "l"(b));
}

// ---------------------------------------------------------------------------
// K0: materialize relative position bias: g_bias[h][i][j]
// ---------------------------------------------------------------------------
__global__ void bias_kernel(const float* __restrict__ rpb,
                            const int*   __restrict__ rel_idx) {
    int idx = blockIdx.x * blockDim.x + threadIdx.x;
    if (idx < HEADS * NTOK * NTOK) {
        int h = idx / (NTOK * NTOK);
        int r = idx % (NTOK * NTOK);
        g_bias[idx] = rpb[rel_idx[r] * HEADS + h];
    }
}

// ---------------------------------------------------------------------------
// K1: QKV GEMM.  C(262144 x 576) = X(262144 x 192) * W^T + b
// Block = 64 rows (one window) x 64 cols. 256 threads, 4x4 microtile, FFMA2.
// Epilogue scatters into g_qkv (b,s,h,n,d), scaling q by d^-0.5.
// ---------------------------------------------------------------------------
__global__ void __launch_bounds__(256) qkv_kernel(const float* __restrict__ x,
                                                  const float* __restrict__ w,
                                                  const float* __restrict__ bvec) {
    __shared__ float As[64][36];   // [row][k], padded for 16B-aligned float4 STS
    __shared__ float Bs[32][66];   // [k][col], padded (8B-aligned float2 LDS)

    const int tid = threadIdx.x;
    const int tx  = tid & 15, ty = tid >> 4;
    const int b       = blockIdx.y;
    const int rowBase = b * 64;
    const int colBase = blockIdx.x * 64;

    unsigned long long acc[4][2];
#pragma unroll
    for (int i = 0; i < 4; i++) { acc[i][0] = 0ULL; acc[i][1] = 0ULL; }

    for (int kt = 0; kt < DIM; kt += 32) {
#pragma unroll
        for (int it = 0; it < 2; it++) {
            int idx = tid + it * 256;
            int r = idx >> 3, c4 = (idx & 7) * 4;
            float4 va = *(const float4*)(x + (size_t)(rowBase + r) * DIM + kt + c4);
            *(float4*)(&As[r][c4]) = va;
            float4 vb = *(const float4*)(w + (size_t)(colBase + r) * DIM + kt + c4);
            Bs[c4 + 0][r] = vb.x; Bs[c4 + 1][r] = vb.y;
            Bs[c4 + 2][r] = vb.z; Bs[c4 + 3][r] = vb.w;
        }
        __syncthreads();
#pragma unroll 8
        for (int k = 0; k < 32; k++) {
            unsigned long long b0 = *(const unsigned long long*)(&Bs[k][tx * 4]);
            unsigned long long b1 = *(const unsigned long long*)(&Bs[k][tx * 4 + 2]);
#pragma unroll
            for (int i = 0; i < 4; i++) {
                unsigned long long a = pk2(As[ty * 4 + i][k]);
                ffma2(acc[i][0], a, b0);
                ffma2(acc[i][1], a, b1);
            }
        }
        __syncthreads();
    }

    // Epilogue: +bias, scale q, scatter to (b,s,h,n,d)
    const float scale = 0.17677669529663687f;   // 32^-0.5
    const int o0 = colBase + tx * 4;            // 4 contiguous output cols
    const int s  = o0 / DIM;                    // 0=q, 1=k, 2=v (tile never crosses)
    const int h  = (o0 % DIM) / HDIM;           // 4 cols stay within one head
    const int dd = o0 % HDIM;
    const float mul = (s == 0) ? scale : 1.0f;

#pragma unroll
    for (int i = 0; i < 4; i++) {
        int n = ty * 4 + i;
        float2 p0 = upk2(acc[i][0]);
        float2 p1 = upk2(acc[i][1]);
        float4 o4 = make_float4((p0.x + bvec[o0 + 0]) * mul,
                                (p0.y + bvec[o0 + 1]) * mul,
                                (p1.x + bvec[o0 + 2]) * mul,
                                (p1.y + bvec[o0 + 3]) * mul);
        *(float4*)(g_qkv + (((size_t)(b * 3 + s) * HEADS + h) * NTOK + n) * HDIM + dd) = o4;
    }
}

// ---------------------------------------------------------------------------
// K2: attention per (window, head). 24576 blocks x 256 threads.
//   logits = q_scaled . k^T + bias ; softmax rows ; out = attn . v
// ---------------------------------------------------------------------------
__global__ void __launch_bounds__(256) attn_kernel() {
    __shared__ float qs [64][36];   // [n][d]
    __shared__ float kts[32][66];   // [d][n]  (k transposed)
    __shared__ float vs [64][36];   // [n][d]
    __shared__ float as_[64][66];   // attn weights

    const int tid = threadIdx.x;
    const int bh  = blockIdx.x;
    const int b   = bh / HEADS, h = bh % HEADS;

    const float* qg = g_qkv + (((size_t)(b * 3 + 0) * HEADS + h) * NTOK) * HDIM;
    const float* kg = g_qkv + (((size_t)(b * 3 + 1) * HEADS + h) * NTOK) * HDIM;
    const float* vg = g_qkv + (((size_t)(b * 3 + 2) * HEADS + h) * NTOK) * HDIM;

#pragma unroll
    for (int it = 0; it < 2; it++) {
        int idx = tid + it * 256;
        int n = idx >> 3, c4 = (idx & 7) * 4;
        float4 q4 = *(const float4*)(qg + n * HDIM + c4);
        *(float4*)(&qs[n][c4]) = q4;
        float4 k4 = *(const float4*)(kg + n * HDIM + c4);
        kts[c4 + 0][n] = k4.x; kts[c4 + 1][n] = k4.y;
        kts[c4 + 2][n] = k4.z; kts[c4 + 3][n] = k4.w;
        float4 v4 = *(const float4*)(vg + n * HDIM + c4);
        *(float4*)(&vs[n][c4]) = v4;
    }
    __syncthreads();

    const int tx = tid & 15, ty = tid >> 4;   // rows ty*4..+3, cols tx*4..+3

    // init accumulators with bias (logit = q.k + bias)
    unsigned long long acc[4][2];
#pragma unroll
    for (int i = 0; i < 4; i++) {
        int row = ty * 4 + i;
        float4 bb = *(const float4*)(g_bias + h * (NTOK * NTOK) + row * NTOK + tx * 4);
        acc[i][0] = pk2f(bb.x, bb.y);
        acc[i][1] = pk2f(bb.z, bb.w);
    }
#pragma unroll 8
    for (int k = 0; k < HDIM; k++) {
        unsigned long long b0 = *(const unsigned long long*)(&kts[k][tx * 4]);
        unsigned long long b1 = *(const unsigned long long*)(&kts[k][tx * 4 + 2]);
#pragma unroll
        for (int i = 0; i < 4; i++) {
            unsigned long long a = pk2(qs[ty * 4 + i][k]);
            ffma2(acc[i][0], a, b0);
            ffma2(acc[i][1], a, b1);
        }
    }

    // softmax: each row owned by 16 lanes sharing ty; lane = (ty&1)*16 + tx,
    // so xor-butterfly offsets 1,2,4,8 stay inside the 16-lane group.
#pragma unroll
    for (int i = 0; i < 4; i++) {
        float2 p0 = upk2(acc[i][0]), p1 = upk2(acc[i][1]);
        float m = fmaxf(fmaxf(p0.x, p0.y), fmaxf(p1.x, p1.y));
#pragma unroll
        for (int off = 8; off >= 1; off >>= 1)
            m = fmaxf(m, __shfl_xor_sync(0xffffffffu, m, off));
        float e0 = __expf(p0.x - m), e1 = __expf(p0.y - m);
        float e2 = __expf(p1.x - m), e3 = __expf(p1.y - m);
        float ssum = e0 + e1 + e2 + e3;
#pragma unroll
        for (int off = 8; off >= 1; off >>= 1)
            ssum += __shfl_xor_sync(0xffffffffu, ssum, off);
        float inv = 1.0f / ssum;
        int row = ty * 4 + i;
        as_[row][tx * 4 + 0] = e0 * inv;
        as_[row][tx * 4 + 1] = e1 * inv;
        as_[row][tx * 4 + 2] = e2 * inv;
        as_[row][tx * 4 + 3] = e3 * inv;
    }
    __syncthreads();

    // out[i][dd] = sum_j attn[i][j] * v[j][dd]; thread -> (row i, 8 cols)
    const int i   = tid >> 2;
    const int dd0 = (tid & 3) * 8;
    unsigned long long o[4] = {0ULL, 0ULL, 0ULL, 0ULL};
#pragma unroll 8
    for (int j = 0; j < NTOK; j++) {
        unsigned long long a  = pk2(as_[i][j]);
        unsigned long long v0 = *(const unsigned long long*)(&vs[j][dd0]);
        unsigned long long v1 = *(const unsigned long long*)(&vs[j][dd0 + 2]);
        unsigned long long v2 = *(const unsigned long long*)(&vs[j][dd0 + 4]);
        unsigned long long v3 = *(const unsigned long long*)(&vs[j][dd0 + 6]);
        ffma2(o[0], a, v0); ffma2(o[1], a, v1);
        ffma2(o[2], a, v2); ffma2(o[3], a, v3);
    }
    float* dst = g_att + ((size_t)b * NTOK + i) * DIM + h * HDIM + dd0;
    float2 r0 = upk2(o[0]), r1 = upk2(o[1]), r2 = upk2(o[2]), r3 = upk2(o[3]);
    *(float4*)(dst)     = make_float4(r0.x, r0.y, r1.x, r1.y);
    *(float4*)(dst + 4) = make_float4(r2.x, r2.y, r3.x, r3.y);
}

// ---------------------------------------------------------------------------
// K3: proj GEMM. out(262144 x 192) = g_att * proj_w^T + proj_b
// ---------------------------------------------------------------------------
__global__ void __launch_bounds__(256) proj_kernel(const float* __restrict__ w,
                                                   const float* __restrict__ bvec,
                                                   float* __restrict__ out) {
    __shared__ float As[64][36];
    __shared__ float Bs[32][66];

    const int tid = threadIdx.x;
    const int tx  = tid & 15, ty = tid >> 4;
    const size_t rowBase = (size_t)blockIdx.y * 64;
    const int colBase    = blockIdx.x * 64;

    unsigned long long acc[4][2];
#pragma unroll
    for (int i = 0; i < 4; i++) { acc[i][0] = 0ULL; acc[i][1] = 0ULL; }

    for (int kt = 0; kt < DIM; kt += 32) {
#pragma unroll
        for (int it = 0; it < 2; it++) {
            int idx = tid + it * 256;
            int r = idx >> 3, c4 = (idx & 7) * 4;
            float4 va = *(const float4*)(g_att + (rowBase + r) * DIM + kt + c4);
            *(float4*)(&As[r][c4]) = va;
            float4 vb = *(const float4*)(w + (size_t)(colBase + r) * DIM + kt + c4);
            Bs[c4 + 0][r] = vb.x; Bs[c4 + 1][r] = vb.y;
            Bs[c4 + 2][r] = vb.z; Bs[c4 + 3][r] = vb.w;
        }
        __syncthreads();
#pragma unroll 8
        for (int k = 0; k < 32; k++) {
            unsigned long long b0 = *(const unsigned long long*)(&Bs[k][tx * 4]);
            unsigned long long b1 = *(const unsigned long long*)(&Bs[k][tx * 4 + 2]);
#pragma unroll
            for (int i = 0; i < 4; i++) {
                unsigned long long a = pk2(As[ty * 4 + i][k]);
                ffma2(acc[i][0], a, b0);
                ffma2(acc[i][1], a, b1);
            }
        }
        __syncthreads();
    }

    const int c0 = colBase + tx * 4;
#pragma unroll
    for (int i = 0; i < 4; i++) {
        size_t row = rowBase + ty * 4 + i;
        float2 p0 = upk2(acc[i][0]);
        float2 p1 = upk2(acc[i][1]);
        float4 o4 = make_float4(p0.x + bvec[c0 + 0],
                                p0.y + bvec[c0 + 1],
                                p1.x + bvec[c0 + 2],
                                p1.y + bvec[c0 + 3]);
        *(float4*)(out + row * DIM + c0) = o4;
    }
}

// ---------------------------------------------------------------------------
// Launch
// ---------------------------------------------------------------------------
extern "C" void kernel_launch(void* const* d_in, const int* in_sizes, int n_in,
                              void* d_out, int out_size) {
    (void)in_sizes; (void)n_in; (void)out_size;
    const float* x      = (const float*)d_in[0];
    const float* qkv_w  = (const float*)d_in[1];
    const float* qkv_b  = (const float*)d_in[2];
    const float* proj_w = (const float*)d_in[3];
    const float* proj_b = (const float*)d_in[4];
    const float* rpb    = (const float*)d_in[5];
    const int*   relid  = (const int*)d_in[6];
    float* out = (float*)d_out;

    bias_kernel<<<(HEADS * NTOK * NTOK + 255) / 256, 256>>>(rpb, relid);
    qkv_kernel<<<dim3(3 * DIM / 64, NWIN), 256>>>(x, qkv_w, qkv_b);
    attn_kernel<<<NWIN * HEADS, 256>>>();
    proj_kernel<<<dim3(DIM / 64, NWIN), 256>>>(proj_w, proj_b, out);
}

// round 5
// speedup vs baseline: 1.0006x; 1.0006x over previous
#include <cuda_runtime.h>
#include <cstdint>

#define DIM   192
#define HEADS 6
#define HDIM  32
#define NTOK  64
#define NWIN  4096

// ---------------------------------------------------------------------------
// Scratch (static device globals — no allocation in kernel_launch)
// ---------------------------------------------------------------------------
// qkv laid out as (b, s, h, n, d): each (b,s,h) tile is a contiguous 64x32 block
__device__ float g_qkv[(size_t)NWIN * 3 * HEADS * NTOK * HDIM];   // ~604 MB
__device__ float g_att[(size_t)NWIN * NTOK * DIM];                // ~201 MB
__device__ float g_bias[HEADS * NTOK * NTOK];                     // 96 KB

// ---------------------------------------------------------------------------
// Packed f32x2 helpers (Blackwell FFMA2 path — 2 FMAs per instruction)
// ---------------------------------------------------------------------------
__device__ __forceinline__ unsigned long long pk2(float x) {
    unsigned long long r;
    unsigned int b = __float_as_uint(x);
    asm("mov.b64 %0, {%1, %1};" : "=l"(r) : "r"(b));
    return r;
}
__device__ __forceinline__ unsigned long long pk2f(float lo, float hi) {
    unsigned long long r;
    asm("mov.b64 %0, {%1, %2};" : "=l"(r) : "r"(__float_as_uint(lo)), "r"(__float_as_uint(hi)));
    return r;
}
__device__ __forceinline__ float2 upk2(unsigned long long v) {
    unsigned int lo, hi;
    asm("mov.b64 {%0, %1}, %2;" : "=r"(lo), "=r"(hi) : "l"(v));
    return make_float2(__uint_as_float(lo), __uint_as_float(hi));
}
__device__ __forceinline__ void ffma2(unsigned long long& d,
                                      unsigned long long a,
                                      unsigned long long b) {
    asm("fma.rn.f32x2 %0, %1, %2, %0;" : "+l"(d) : "l"(a), "l"(b));
}

// ---------------------------------------------------------------------------
// K0: materialize relative position bias: g_bias[h][i][j]
// ---------------------------------------------------------------------------
__global__ void bias_kernel(const float* __restrict__ rpb,
                            const int*   __restrict__ rel_idx) {
    int idx = blockIdx.x * blockDim.x + threadIdx.x;
    if (idx < HEADS * NTOK * NTOK) {
        int h = idx / (NTOK * NTOK);
        int r = idx % (NTOK * NTOK);
        g_bias[idx] = rpb[rel_idx[r] * HEADS + h];
    }
}

// ---------------------------------------------------------------------------
// K1: QKV GEMM.  C(262144 x 576) = X(262144 x 192) * W^T + b
// Block = 64 rows (one window) x 64 cols. 256 threads, 4x4 microtile, FFMA2.
// Epilogue scatters into g_qkv (b,s,h,n,d), scaling q by d^-0.5.
// ---------------------------------------------------------------------------
__global__ void __launch_bounds__(256) qkv_kernel(const float* __restrict__ x,
                                                  const float* __restrict__ w,
                                                  const float* __restrict__ bvec) {
    __shared__ float As[64][36];   // [row][k], padded for 16B-aligned float4 STS
    __shared__ float Bs[32][66];   // [k][col], padded (8B-aligned float2 LDS)

    const int tid = threadIdx.x;
    const int tx  = tid & 15, ty = tid >> 4;
    const int b       = blockIdx.y;
    const int rowBase = b * 64;
    const int colBase = blockIdx.x * 64;

    unsigned long long acc[4][2];
#pragma unroll
    for (int i = 0; i < 4; i++) { acc[i][0] = 0ULL; acc[i][1] = 0ULL; }

    for (int kt = 0; kt < DIM; kt += 32) {
#pragma unroll
        for (int it = 0; it < 2; it++) {
            int idx = tid + it * 256;
            int r = idx >> 3, c4 = (idx & 7) * 4;
            float4 va = *(const float4*)(x + (size_t)(rowBase + r) * DIM + kt + c4);
            *(float4*)(&As[r][c4]) = va;
            float4 vb = *(const float4*)(w + (size_t)(colBase + r) * DIM + kt + c4);
            Bs[c4 + 0][r] = vb.x; Bs[c4 + 1][r] = vb.y;
            Bs[c4 + 2][r] = vb.z; Bs[c4 + 3][r] = vb.w;
        }
        __syncthreads();
#pragma unroll 8
        for (int k = 0; k < 32; k++) {
            unsigned long long b0 = *(const unsigned long long*)(&Bs[k][tx * 4]);
            unsigned long long b1 = *(const unsigned long long*)(&Bs[k][tx * 4 + 2]);
#pragma unroll
            for (int i = 0; i < 4; i++) {
                unsigned long long a = pk2(As[ty * 4 + i][k]);
                ffma2(acc[i][0], a, b0);
                ffma2(acc[i][1], a, b1);
            }
        }
        __syncthreads();
    }

    // Epilogue: +bias, scale q, scatter to (b,s,h,n,d)
    const float scale = 0.17677669529663687f;   // 32^-0.5
    const int o0 = colBase + tx * 4;            // 4 contiguous output cols
    const int s  = o0 / DIM;                    // 0=q, 1=k, 2=v (tile never crosses)
    const int h  = (o0 % DIM) / HDIM;           // 4 cols stay within one head
    const int dd = o0 % HDIM;
    const float mul = (s == 0) ? scale : 1.0f;

#pragma unroll
    for (int i = 0; i < 4; i++) {
        int n = ty * 4 + i;
        float2 p0 = upk2(acc[i][0]);
        float2 p1 = upk2(acc[i][1]);
        float4 o4 = make_float4((p0.x + bvec[o0 + 0]) * mul,
                                (p0.y + bvec[o0 + 1]) * mul,
                                (p1.x + bvec[o0 + 2]) * mul,
                                (p1.y + bvec[o0 + 3]) * mul);
        *(float4*)(g_qkv + (((size_t)(b * 3 + s) * HEADS + h) * NTOK + n) * HDIM + dd) = o4;
    }
}

// ---------------------------------------------------------------------------
// K2: attention per (window, head). 24576 blocks x 256 threads.
//   logits = q_scaled . k^T + bias ; softmax rows ; out = attn . v
// ---------------------------------------------------------------------------
__global__ void __launch_bounds__(256) attn_kernel() {
    __shared__ float qs [64][36];   // [n][d]
    __shared__ float kts[32][66];   // [d][n]  (k transposed)
    __shared__ float vs [64][36];   // [n][d]
    __shared__ float as_[64][66];   // attn weights

    const int tid = threadIdx.x;
    const int bh  = blockIdx.x;
    const int b   = bh / HEADS, h = bh % HEADS;

    const float* qg = g_qkv + (((size_t)(b * 3 + 0) * HEADS + h) * NTOK) * HDIM;
    const float* kg = g_qkv + (((size_t)(b * 3 + 1) * HEADS + h) * NTOK) * HDIM;
    const float* vg = g_qkv + (((size_t)(b * 3 + 2) * HEADS + h) * NTOK) * HDIM;

#pragma unroll
    for (int it = 0; it < 2; it++) {
        int idx = tid + it * 256;
        int n = idx >> 3, c4 = (idx & 7) * 4;
        float4 q4 = *(const float4*)(qg + n * HDIM + c4);
        *(float4*)(&qs[n][c4]) = q4;
        float4 k4 = *(const float4*)(kg + n * HDIM + c4);
        kts[c4 + 0][n] = k4.x; kts[c4 + 1][n] = k4.y;
        kts[c4 + 2][n] = k4.z; kts[c4 + 3][n] = k4.w;
        float4 v4 = *(const float4*)(vg + n * HDIM + c4);
        *(float4*)(&vs[n][c4]) = v4;
    }
    __syncthreads();

    const int tx = tid & 15, ty = tid >> 4;   // rows ty*4..+3, cols tx*4..+3

    // init accumulators with bias (logit = q.k + bias)
    unsigned long long acc[4][2];
#pragma unroll
    for (int i = 0; i < 4; i++) {
        int row = ty * 4 + i;
        float4 bb = *(const float4*)(g_bias + h * (NTOK * NTOK) + row * NTOK + tx * 4);
        acc[i][0] = pk2f(bb.x, bb.y);
        acc[i][1] = pk2f(bb.z, bb.w);
    }
#pragma unroll 8
    for (int k = 0; k < HDIM; k++) {
        unsigned long long b0 = *(const unsigned long long*)(&kts[k][tx * 4]);
        unsigned long long b1 = *(const unsigned long long*)(&kts[k][tx * 4 + 2]);
#pragma unroll
        for (int i = 0; i < 4; i++) {
            unsigned long long a = pk2(qs[ty * 4 + i][k]);
            ffma2(acc[i][0], a, b0);
            ffma2(acc[i][1], a, b1);
        }
    }

    // softmax: each row owned by 16 lanes sharing ty; lane = (ty&1)*16 + tx,
    // so xor-butterfly offsets 1,2,4,8 stay inside the 16-lane group.
#pragma unroll
    for (int i = 0; i < 4; i++) {
        float2 p0 = upk2(acc[i][0]), p1 = upk2(acc[i][1]);
        float m = fmaxf(fmaxf(p0.x, p0.y), fmaxf(p1.x, p1.y));
#pragma unroll
        for (int off = 8; off >= 1; off >>= 1)
            m = fmaxf(m, __shfl_xor_sync(0xffffffffu, m, off));
        float e0 = __expf(p0.x - m), e1 = __expf(p0.y - m);
        float e2 = __expf(p1.x - m), e3 = __expf(p1.y - m);
        float ssum = e0 + e1 + e2 + e3;
#pragma unroll
        for (int off = 8; off >= 1; off >>= 1)
            ssum += __shfl_xor_sync(0xffffffffu, ssum, off);
        float inv = 1.0f / ssum;
        int row = ty * 4 + i;
        as_[row][tx * 4 + 0] = e0 * inv;
        as_[row][tx * 4 + 1] = e1 * inv;
        as_[row][tx * 4 + 2] = e2 * inv;
        as_[row][tx * 4 + 3] = e3 * inv;
    }
    __syncthreads();

    // out[i][dd] = sum_j attn[i][j] * v[j][dd]; thread -> (row i, 8 cols)
    const int i   = tid >> 2;
    const int dd0 = (tid & 3) * 8;
    unsigned long long o[4] = {0ULL, 0ULL, 0ULL, 0ULL};
#pragma unroll 8
    for (int j = 0; j < NTOK; j++) {
        unsigned long long a  = pk2(as_[i][j]);
        unsigned long long v0 = *(const unsigned long long*)(&vs[j][dd0]);
        unsigned long long v1 = *(const unsigned long long*)(&vs[j][dd0 + 2]);
        unsigned long long v2 = *(const unsigned long long*)(&vs[j][dd0 + 4]);
        unsigned long long v3 = *(const unsigned long long*)(&vs[j][dd0 + 6]);
        ffma2(o[0], a, v0); ffma2(o[1], a, v1);
        ffma2(o[2], a, v2); ffma2(o[3], a, v3);
    }
    float* dst = g_att + ((size_t)b * NTOK + i) * DIM + h * HDIM + dd0;
    float2 r0 = upk2(o[0]), r1 = upk2(o[1]), r2 = upk2(o[2]), r3 = upk2(o[3]);
    *(float4*)(dst)     = make_float4(r0.x, r0.y, r1.x, r1.y);
    *(float4*)(dst + 4) = make_float4(r2.x, r2.y, r3.x, r3.y);
}

// ---------------------------------------------------------------------------
// K3: proj GEMM. out(262144 x 192) = g_att * proj_w^T + proj_b
// ---------------------------------------------------------------------------
__global__ void __launch_bounds__(256) proj_kernel(const float* __restrict__ w,
                                                   const float* __restrict__ bvec,
                                                   float* __restrict__ out) {
    __shared__ float As[64][36];
    __shared__ float Bs[32][66];

    const int tid = threadIdx.x;
    const int tx  = tid & 15, ty = tid >> 4;
    const size_t rowBase = (size_t)blockIdx.y * 64;
    const int colBase    = blockIdx.x * 64;

    unsigned long long acc[4][2];
#pragma unroll
    for (int i = 0; i < 4; i++) { acc[i][0] = 0ULL; acc[i][1] = 0ULL; }

    for (int kt = 0; kt < DIM; kt += 32) {
#pragma unroll
        for (int it = 0; it < 2; it++) {
            int idx = tid + it * 256;
            int r = idx >> 3, c4 = (idx & 7) * 4;
            float4 va = *(const float4*)(g_att + (rowBase + r) * DIM + kt + c4);
            *(float4*)(&As[r][c4]) = va;
            float4 vb = *(const float4*)(w + (size_t)(colBase + r) * DIM + kt + c4);
            Bs[c4 + 0][r] = vb.x; Bs[c4 + 1][r] = vb.y;
            Bs[c4 + 2][r] = vb.z; Bs[c4 + 3][r] = vb.w;
        }
        __syncthreads();
#pragma unroll 8
        for (int k = 0; k < 32; k++) {
            unsigned long long b0 = *(const unsigned long long*)(&Bs[k][tx * 4]);
            unsigned long long b1 = *(const unsigned long long*)(&Bs[k][tx * 4 + 2]);
#pragma unroll
            for (int i = 0; i < 4; i++) {
                unsigned long long a = pk2(As[ty * 4 + i][k]);
                ffma2(acc[i][0], a, b0);
                ffma2(acc[i][1], a, b1);
            }
        }
        __syncthreads();
    }

    const int c0 = colBase + tx * 4;
#pragma unroll
    for (int i = 0; i < 4; i++) {
        size_t row = rowBase + ty * 4 + i;
        float2 p0 = upk2(acc[i][0]);
        float2 p1 = upk2(acc[i][1]);
        float4 o4 = make_float4(p0.x + bvec[c0 + 0],
                                p0.y + bvec[c0 + 1],
                                p1.x + bvec[c0 + 2],
                                p1.y + bvec[c0 + 3]);
        *(float4*)(out + row * DIM + c0) = o4;
    }
}

// ---------------------------------------------------------------------------
// Launch
// ---------------------------------------------------------------------------
extern "C" void kernel_launch(void* const* d_in, const int* in_sizes, int n_in,
                              void* d_out, int out_size) {
    (void)in_sizes; (void)n_in; (void)out_size;
    const float* x      = (const float*)d_in[0];
    const float* qkv_w  = (const float*)d_in[1];
    const float* qkv_b  = (const float*)d_in[2];
    const float* proj_w = (const float*)d_in[3];
    const float* proj_b = (const float*)d_in[4];
    const float* rpb    = (const float*)d_in[5];
    const int*   relid  = (const int*)d_in[6];
    float* out = (float*)d_out;

    bias_kernel<<<(HEADS * NTOK * NTOK + 255) / 256, 256>>>(rpb, relid);
    qkv_kernel<<<dim3(3 * DIM / 64, NWIN), 256>>>(x, qkv_w, qkv_b);
    attn_kernel<<<NWIN * HEADS, 256>>>();
    proj_kernel<<<dim3(DIM / 64, NWIN), 256>>>(proj_w, proj_b, out);
}

// round 6
// speedup vs baseline: 1.0015x; 1.0008x over previous
#include <cuda_runtime.h>
#include <cstdint>

#define DIM   192
#define HEADS 6
#define HDIM  32
#define NTOK  64
#define NWIN  4096

// ---------------------------------------------------------------------------
// Scratch (static device globals — no allocation in kernel_launch)
// ---------------------------------------------------------------------------
// qkv laid out as (b, s, h, n, d): each (b,s,h) tile is a contiguous 64x32 block
__device__ float g_qkv[(size_t)NWIN * 3 * HEADS * NTOK * HDIM];   // ~604 MB
__device__ float g_att[(size_t)NWIN * NTOK * DIM];                // ~201 MB
__device__ float g_bias[HEADS * NTOK * NTOK];                     // 96 KB

// ---------------------------------------------------------------------------
// Packed f32x2 helpers (Blackwell FFMA2 path — 2 FMAs per instruction)
// ---------------------------------------------------------------------------
__device__ __forceinline__ unsigned long long pk2(float x) {
    unsigned long long r;
    unsigned int b = __float_as_uint(x);
    asm("mov.b64 %0, {%1, %1};" : "=l"(r) : "r"(b));
    return r;
}
__device__ __forceinline__ unsigned long long pk2f(float lo, float hi) {
    unsigned long long r;
    asm("mov.b64 %0, {%1, %2};" : "=l"(r) : "r"(__float_as_uint(lo)), "r"(__float_as_uint(hi)));
    return r;
}
__device__ __forceinline__ float2 upk2(unsigned long long v) {
    unsigned int lo, hi;
    asm("mov.b64 {%0, %1}, %2;" : "=r"(lo), "=r"(hi) : "l"(v));
    return make_float2(__uint_as_float(lo), __uint_as_float(hi));
}
__device__ __forceinline__ void ffma2(unsigned long long& d,
                                      unsigned long long a,
                                      unsigned long long b) {
    asm("fma.rn.f32x2 %0, %1, %2, %0;" : "+l"(d) : "l"(a), "l"(b));
}

// ---------------------------------------------------------------------------
// K0: materialize relative position bias: g_bias[h][i][j]
// ---------------------------------------------------------------------------
__global__ void bias_kernel(const float* __restrict__ rpb,
                            const int*   __restrict__ rel_idx) {
    int idx = blockIdx.x * blockDim.x + threadIdx.x;
    if (idx < HEADS * NTOK * NTOK) {
        int h = idx / (NTOK * NTOK);
        int r = idx % (NTOK * NTOK);
        g_bias[idx] = rpb[rel_idx[r] * HEADS + h];
    }
}

// ---------------------------------------------------------------------------
// K1: QKV GEMM.  C(262144 x 576) = X(262144 x 192) * W^T + b
// Block = 64 rows (one window) x 64 cols. 256 threads, 4x4 microtile, FFMA2.
// Epilogue scatters into g_qkv (b,s,h,n,d), scaling q by d^-0.5.
// ---------------------------------------------------------------------------
__global__ void __launch_bounds__(256) qkv_kernel(const float* __restrict__ x,
                                                  const float* __restrict__ w,
                                                  const float* __restrict__ bvec) {
    __shared__ float As[64][36];   // [row][k], padded for 16B-aligned float4 STS
    __shared__ float Bs[32][66];   // [k][col], padded (8B-aligned float2 LDS)

    const int tid = threadIdx.x;
    const int tx  = tid & 15, ty = tid >> 4;
    const int b       = blockIdx.y;
    const int rowBase = b * 64;
    const int colBase = blockIdx.x * 64;

    unsigned long long acc[4][2];
#pragma unroll
    for (int i = 0; i < 4; i++) { acc[i][0] = 0ULL; acc[i][1] = 0ULL; }

    for (int kt = 0; kt < DIM; kt += 32) {
#pragma unroll
        for (int it = 0; it < 2; it++) {
            int idx = tid + it * 256;
            int r = idx >> 3, c4 = (idx & 7) * 4;
            float4 va = *(const float4*)(x + (size_t)(rowBase + r) * DIM + kt + c4);
            *(float4*)(&As[r][c4]) = va;
            float4 vb = *(const float4*)(w + (size_t)(colBase + r) * DIM + kt + c4);
            Bs[c4 + 0][r] = vb.x; Bs[c4 + 1][r] = vb.y;
            Bs[c4 + 2][r] = vb.z; Bs[c4 + 3][r] = vb.w;
        }
        __syncthreads();
#pragma unroll 8
        for (int k = 0; k < 32; k++) {
            unsigned long long b0 = *(const unsigned long long*)(&Bs[k][tx * 4]);
            unsigned long long b1 = *(const unsigned long long*)(&Bs[k][tx * 4 + 2]);
#pragma unroll
            for (int i = 0; i < 4; i++) {
                unsigned long long a = pk2(As[ty * 4 + i][k]);
                ffma2(acc[i][0], a, b0);
                ffma2(acc[i][1], a, b1);
            }
        }
        __syncthreads();
    }

    // Epilogue: +bias, scale q, scatter to (b,s,h,n,d)
    const float scale = 0.17677669529663687f;   // 32^-0.5
    const int o0 = colBase + tx * 4;            // 4 contiguous output cols
    const int s  = o0 / DIM;                    // 0=q, 1=k, 2=v (tile never crosses)
    const int h  = (o0 % DIM) / HDIM;           // 4 cols stay within one head
    const int dd = o0 % HDIM;
    const float mul = (s == 0) ? scale : 1.0f;

#pragma unroll
    for (int i = 0; i < 4; i++) {
        int n = ty * 4 + i;
        float2 p0 = upk2(acc[i][0]);
        float2 p1 = upk2(acc[i][1]);
        float4 o4 = make_float4((p0.x + bvec[o0 + 0]) * mul,
                                (p0.y + bvec[o0 + 1]) * mul,
                                (p1.x + bvec[o0 + 2]) * mul,
                                (p1.y + bvec[o0 + 3]) * mul);
        *(float4*)(g_qkv + (((size_t)(b * 3 + s) * HEADS + h) * NTOK + n) * HDIM + dd) = o4;
    }
}

// ---------------------------------------------------------------------------
// K2: attention per (window, head). 24576 blocks x 256 threads.
//   logits = q_scaled . k^T + bias ; softmax rows ; out = attn . v
// ---------------------------------------------------------------------------
__global__ void __launch_bounds__(256) attn_kernel() {
    __shared__ float qs [64][36];   // [n][d]
    __shared__ float kts[32][66];   // [d][n]  (k transposed)
    __shared__ float vs [64][36];   // [n][d]
    __shared__ float as_[64][66];   // attn weights

    const int tid = threadIdx.x;
    const int bh  = blockIdx.x;
    const int b   = bh / HEADS, h = bh % HEADS;

    const float* qg = g_qkv + (((size_t)(b * 3 + 0) * HEADS + h) * NTOK) * HDIM;
    const float* kg = g_qkv + (((size_t)(b * 3 + 1) * HEADS + h) * NTOK) * HDIM;
    const float* vg = g_qkv + (((size_t)(b * 3 + 2) * HEADS + h) * NTOK) * HDIM;

#pragma unroll
    for (int it = 0; it < 2; it++) {
        int idx = tid + it * 256;
        int n = idx >> 3, c4 = (idx & 7) * 4;
        float4 q4 = *(const float4*)(qg + n * HDIM + c4);
        *(float4*)(&qs[n][c4]) = q4;
        float4 k4 = *(const float4*)(kg + n * HDIM + c4);
        kts[c4 + 0][n] = k4.x; kts[c4 + 1][n] = k4.y;
        kts[c4 + 2][n] = k4.z; kts[c4 + 3][n] = k4.w;
        float4 v4 = *(const float4*)(vg + n * HDIM + c4);
        *(float4*)(&vs[n][c4]) = v4;
    }
    __syncthreads();

    const int tx = tid & 15, ty = tid >> 4;   // rows ty*4..+3, cols tx*4..+3

    // init accumulators with bias (logit = q.k + bias)
    unsigned long long acc[4][2];
#pragma unroll
    for (int i = 0; i < 4; i++) {
        int row = ty * 4 + i;
        float4 bb = *(const float4*)(g_bias + h * (NTOK * NTOK) + row * NTOK + tx * 4);
        acc[i][0] = pk2f(bb.x, bb.y);
        acc[i][1] = pk2f(bb.z, bb.w);
    }
#pragma unroll 8
    for (int k = 0; k < HDIM; k++) {
        unsigned long long b0 = *(const unsigned long long*)(&kts[k][tx * 4]);
        unsigned long long b1 = *(const unsigned long long*)(&kts[k][tx * 4 + 2]);
#pragma unroll
        for (int i = 0; i < 4; i++) {
            unsigned long long a = pk2(qs[ty * 4 + i][k]);
            ffma2(acc[i][0], a, b0);
            ffma2(acc[i][1], a, b1);
        }
    }

    // softmax: each row owned by 16 lanes sharing ty; lane = (ty&1)*16 + tx,
    // so xor-butterfly offsets 1,2,4,8 stay inside the 16-lane group.
#pragma unroll
    for (int i = 0; i < 4; i++) {
        float2 p0 = upk2(acc[i][0]), p1 = upk2(acc[i][1]);
        float m = fmaxf(fmaxf(p0.x, p0.y), fmaxf(p1.x, p1.y));
#pragma unroll
        for (int off = 8; off >= 1; off >>= 1)
            m = fmaxf(m, __shfl_xor_sync(0xffffffffu, m, off));
        float e0 = __expf(p0.x - m), e1 = __expf(p0.y - m);
        float e2 = __expf(p1.x - m), e3 = __expf(p1.y - m);
        float ssum = e0 + e1 + e2 + e3;
#pragma unroll
        for (int off = 8; off >= 1; off >>= 1)
            ssum += __shfl_xor_sync(0xffffffffu, ssum, off);
        float inv = 1.0f / ssum;
        int row = ty * 4 + i;
        as_[row][tx * 4 + 0] = e0 * inv;
        as_[row][tx * 4 + 1] = e1 * inv;
        as_[row][tx * 4 + 2] = e2 * inv;
        as_[row][tx * 4 + 3] = e3 * inv;
    }
    __syncthreads();

    // out[i][dd] = sum_j attn[i][j] * v[j][dd]; thread -> (row i, 8 cols)
    const int i   = tid >> 2;
    const int dd0 = (tid & 3) * 8;
    unsigned long long o[4] = {0ULL, 0ULL, 0ULL, 0ULL};
#pragma unroll 8
    for (int j = 0; j < NTOK; j++) {
        unsigned long long a  = pk2(as_[i][j]);
        unsigned long long v0 = *(const unsigned long long*)(&vs[j][dd0]);
        unsigned long long v1 = *(const unsigned long long*)(&vs[j][dd0 + 2]);
        unsigned long long v2 = *(const unsigned long long*)(&vs[j][dd0 + 4]);
        unsigned long long v3 = *(const unsigned long long*)(&vs[j][dd0 + 6]);
        ffma2(o[0], a, v0); ffma2(o[1], a, v1);
        ffma2(o[2], a, v2); ffma2(o[3], a, v3);
    }
    float* dst = g_att + ((size_t)b * NTOK + i) * DIM + h * HDIM + dd0;
    float2 r0 = upk2(o[0]), r1 = upk2(o[1]), r2 = upk2(o[2]), r3 = upk2(o[3]);
    *(float4*)(dst)     = make_float4(r0.x, r0.y, r1.x, r1.y);
    *(float4*)(dst + 4) = make_float4(r2.x, r2.y, r3.x, r3.y);
}

// ---------------------------------------------------------------------------
// K3: proj GEMM. out(262144 x 192) = g_att * proj_w^T + proj_b
// ---------------------------------------------------------------------------
__global__ void __launch_bounds__(256) proj_kernel(const float* __restrict__ w,
                                                   const float* __restrict__ bvec,
                                                   float* __restrict__ out) {
    __shared__ float As[64][36];
    __shared__ float Bs[32][66];

    const int tid = threadIdx.x;
    const int tx  = tid & 15, ty = tid >> 4;
    const size_t rowBase = (size_t)blockIdx.y * 64;
    const int colBase    = blockIdx.x * 64;

    unsigned long long acc[4][2];
#pragma unroll
    for (int i = 0; i < 4; i++) { acc[i][0] = 0ULL; acc[i][1] = 0ULL; }

    for (int kt = 0; kt < DIM; kt += 32) {
#pragma unroll
        for (int it = 0; it < 2; it++) {
            int idx = tid + it * 256;
            int r = idx >> 3, c4 = (idx & 7) * 4;
            float4 va = *(const float4*)(g_att + (rowBase + r) * DIM + kt + c4);
            *(float4*)(&As[r][c4]) = va;
            float4 vb = *(const float4*)(w + (size_t)(colBase + r) * DIM + kt + c4);
            Bs[c4 + 0][r] = vb.x; Bs[c4 + 1][r] = vb.y;
            Bs[c4 + 2][r] = vb.z; Bs[c4 + 3][r] = vb.w;
        }
        __syncthreads();
#pragma unroll 8
        for (int k = 0; k < 32; k++) {
            unsigned long long b0 = *(const unsigned long long*)(&Bs[k][tx * 4]);
            unsigned long long b1 = *(const unsigned long long*)(&Bs[k][tx * 4 + 2]);
#pragma unroll
            for (int i = 0; i < 4; i++) {
                unsigned long long a = pk2(As[ty * 4 + i][k]);
                ffma2(acc[i][0], a, b0);
                ffma2(acc[i][1], a, b1);
            }
        }
        __syncthreads();
    }

    const int c0 = colBase + tx * 4;
#pragma unroll
    for (int i = 0; i < 4; i++) {
        size_t row = rowBase + ty * 4 + i;
        float2 p0 = upk2(acc[i][0]);
        float2 p1 = upk2(acc[i][1]);
        float4 o4 = make_float4(p0.x + bvec[c0 + 0],
                                p0.y + bvec[c0 + 1],
                                p1.x + bvec[c0 + 2],
                                p1.y + bvec[c0 + 3]);
        *(float4*)(out + row * DIM + c0) = o4;
    }
}

// ---------------------------------------------------------------------------
// Launch
// ---------------------------------------------------------------------------
extern "C" void kernel_launch(void* const* d_in, const int* in_sizes, int n_in,
                              void* d_out, int out_size) {
    (void)in_sizes; (void)n_in; (void)out_size;
    const float* x      = (const float*)d_in[0];
    const float* qkv_w  = (const float*)d_in[1];
    const float* qkv_b  = (const float*)d_in[2];
    const float* proj_w = (const float*)d_in[3];
    const float* proj_b = (const float*)d_in[4];
    const float* rpb    = (const float*)d_in[5];
    const int*   relid  = (const int*)d_in[6];
    float* out = (float*)d_out;

    bias_kernel<<<(HEADS * NTOK * NTOK + 255) / 256, 256>>>(rpb, relid);
    qkv_kernel<<<dim3(3 * DIM / 64, NWIN), 256>>>(x, qkv_w, qkv_b);
    attn_kernel<<<NWIN * HEADS, 256>>>();
    proj_kernel<<<dim3(DIM / 64, NWIN), 256>>>(proj_w, proj_b, out);
}